// round 12
// baseline (speedup 1.0000x reference)
#include <cuda_runtime.h>
#include <cuda_bf16.h>
#include <math_constants.h>
#include <cstdint>

#define NPTS 8192
#define BATCH 4
#define KNNK 10

// ---------------- scratch arena (no allocation allowed) ----------------
#define O_X0     0u
#define O_IDX    196608u
#define O_X1     524288u
#define O_X2     2621440u
#define O_X3     4718592u
#define O_X4     6815744u
#define O_X5     13107200u
#define O_PMAX   46661632u
#define O_X5MAX  46792704u
#define O_BIAS   46796800u
#define O_Y1     46797824u
#define O_Y2     55186432u
#define O_Y3     63575040u
#define O_XHI    67769344u   // 2,097,152 bf16 = 1,048,576 floats
#define O_XLO    68817920u
#define O_NORM   69866496u   // 32768 floats
#define SCRATCH_FLOATS 69899264u

__device__ __align__(16) float g_scratch[SCRATCH_FLOATS];

// ---------------- f32x2 packed helpers (sm_103a) ----------------
__device__ __forceinline__ void unpack2(unsigned long long v, float& lo, float& hi) {
    asm("mov.b64 {%0, %1}, %2;" : "=f"(lo), "=f"(hi) : "l"(v));
}
__device__ __forceinline__ unsigned long long fma2(unsigned long long a,
                                                   unsigned long long b,
                                                   unsigned long long c) {
    unsigned long long d;
    asm("fma.rn.f32x2 %0, %1, %2, %3;" : "=l"(d) : "l"(a), "l"(b), "l"(c));
    return d;
}

// ---------------- warp-mma helpers (target-independent PTX) ----------------
__device__ __forceinline__ uint32_t smem_to_u32(const void* p) {
    uint32_t a;
    asm("{ .reg .u64 t; cvta.to.shared.u64 t, %1; cvt.u32.u64 %0, t; }" : "=r"(a) : "l"(p));
    return a;
}
#define SMEM_SWIZZLE_128B(o) ((o) ^ (((o) >> 3) & 0x70))

__device__ __forceinline__ void ldsm_x4(uint32_t a[4], uint32_t addr) {
    asm volatile("ldmatrix.sync.aligned.m8n8.x4.shared.b16 {%0,%1,%2,%3}, [%4];"
        : "=r"(a[0]), "=r"(a[1]), "=r"(a[2]), "=r"(a[3]) : "r"(addr));
}
__device__ __forceinline__ void ldsm_x2(uint32_t a[2], uint32_t addr) {
    asm volatile("ldmatrix.sync.aligned.m8n8.x2.shared.b16 {%0,%1}, [%2];"
        : "=r"(a[0]), "=r"(a[1]) : "r"(addr));
}
__device__ __forceinline__ void mma16816(float c[4], const uint32_t a[4], const uint32_t b[2]) {
    asm volatile("mma.sync.aligned.m16n8k16.row.col.f32.bf16.bf16.f32 "
        "{%0,%1,%2,%3}, {%4,%5,%6,%7}, {%8,%9}, {%0,%1,%2,%3};"
        : "+f"(c[0]), "+f"(c[1]), "+f"(c[2]), "+f"(c[3])
        : "r"(a[0]), "r"(a[1]), "r"(a[2]), "r"(a[3]), "r"(b[0]), "r"(b[1]));
}

// ---------------- build x0 = concat(targets, targets) ----------------
__global__ void build_x0_kernel(const float* __restrict__ t, float* __restrict__ x0) {
    int i = blockIdx.x * blockDim.x + threadIdx.x;
    if (i < BATCH * NPTS * 6) {
        int pt = i / 6, c = i % 6;
        x0[i] = t[pt * 3 + (c < 3 ? c : c - 3)];
    }
}

// ---------------- fp32 -> bf16 hi/lo split ----------------
__global__ void cvt_split_kernel(const float* __restrict__ x,
                                 __nv_bfloat16* __restrict__ hi,
                                 __nv_bfloat16* __restrict__ lo, int n) {
    int i = blockIdx.x * 256 + threadIdx.x;
    if (i < n) {
        float v = x[i];
        __nv_bfloat16 h = __float2bfloat16(v);
        hi[i] = h;
        lo[i] = __float2bfloat16(v - __bfloat162float(h));
    }
}

// ---------------- squared norms (C=64) ----------------
__global__ void norms_kernel(const float* __restrict__ x, float* __restrict__ norms) {
    int p = blockIdx.x * 256 + threadIdx.x;
    if (p < BATCH * NPTS) {
        const float* row = x + (size_t)p * 64;
        float s = 0.f;
        #pragma unroll
        for (int c = 0; c < 64; c += 4) {
            float4 v = *(const float4*)(row + c);
            s = fmaf(v.x, v.x, s); s = fmaf(v.y, v.y, s);
            s = fmaf(v.z, v.z, s); s = fmaf(v.w, v.w, s);
        }
        norms[p] = s;
    }
}

// ---------------- small-C KNN (C=6), thread per query (R2-proven) ----------------
template<int C>
__global__ void knn_kernel(const float* __restrict__ x, int* __restrict__ idxout) {
    __shared__ float tile[128 * C];
    __shared__ float tnorm[128];
    const int b = blockIdx.y;
    const int q = blockIdx.x * 128 + threadIdx.x;
    const float* xb = x + (size_t)b * NPTS * C;

    float qf[C];
    float qn = 0.f;
    #pragma unroll
    for (int c = 0; c < C; c++) { qf[c] = xb[q * C + c]; qn = fmaf(qf[c], qf[c], qn); }

    float bd[KNNK]; int bi[KNNK];
    #pragma unroll
    for (int i = 0; i < KNNK; i++) { bd[i] = CUDART_INF_F; bi[i] = 0; }

    for (int t0 = 0; t0 < NPTS; t0 += 128) {
        __syncthreads();
        for (int i = threadIdx.x; i < 128 * C; i += 128) tile[i] = xb[t0 * C + i];
        __syncthreads();
        {
            float s = 0.f;
            #pragma unroll
            for (int c = 0; c < C; c++) {
                float v = tile[threadIdx.x * C + c];
                s = fmaf(v, v, s);
            }
            tnorm[threadIdx.x] = s;
        }
        __syncthreads();
        for (int j = 0; j < 128; j++) {
            float d0 = 0.f, d1 = 0.f;
            #pragma unroll
            for (int c = 0; c < C; c += 2) {
                d0 = fmaf(qf[c + 0], tile[j * C + c + 0], d0);
                d1 = fmaf(qf[c + 1], tile[j * C + c + 1], d1);
            }
            float d = qn + tnorm[j] - 2.f * (d0 + d1);
            if (d < bd[KNNK - 1]) {
                bd[KNNK - 1] = d; bi[KNNK - 1] = t0 + j;
                #pragma unroll
                for (int s = KNNK - 1; s > 0; s--) {
                    if (bd[s] < bd[s - 1]) {
                        float td = bd[s]; bd[s] = bd[s - 1]; bd[s - 1] = td;
                        int   ti = bi[s]; bi[s] = bi[s - 1]; bi[s - 1] = ti;
                    }
                }
            }
        }
    }
    int* o = idxout + ((size_t)b * NPTS + q) * KNNK;
    #pragma unroll
    for (int i = 0; i < KNNK; i++) o[i] = bi[i];
}

// ---------------- KNN C=64 on tensor cores (R8 base, A-fragments hoisted) ----------------
// block 128 threads = 4 warps; block owns 128 queries; 128 candidate tiles of 64.
// dot = Ahi@Bhi^T + Ahi@Blo^T + Alo@Bhi^T ; d = |x_j|^2 - 2*dot (ordering exact).
// A fragments are tile-invariant: ldsm'd ONCE into 64 registers before the loop.
#define SM_AHI   0          // 128 rows x 128B (SW128)
#define SM_ALO   16384
#define SM_BHI   32768      // 64 rows x 128B
#define SM_BLO   40960
#define SM_TN    49152      // 64 floats
#define SM_DIST  49408      // 128 x 66 floats
#define SM_KNN_TOTAL 83200

__global__ __launch_bounds__(128)
void knn_mma_kernel(const __nv_bfloat16* __restrict__ xhi,
                    const __nv_bfloat16* __restrict__ xlo,
                    const float* __restrict__ norms,
                    int* __restrict__ idxout) {
    extern __shared__ char smem[];
    const uint32_t sb = smem_to_u32(smem);
    float* tnS  = (float*)(smem + SM_TN);
    float* dist = (float*)(smem + SM_DIST);
    const int tid = threadIdx.x, w = tid >> 5, l = tid & 31;
    const int b = blockIdx.y, q0 = blockIdx.x * 128;
    const __nv_bfloat16* xh = xhi + (size_t)b * NPTS * 64;
    const __nv_bfloat16* xl = xlo + (size_t)b * NPTS * 64;
    const float* nrm = norms + (size_t)b * NPTS;

    // A tiles (queries), SW128 swizzled; row = 64 bf16 = 128B.
    {
        const uint4* sH = (const uint4*)(xh + (size_t)(q0 + tid) * 64);
        const uint4* sL = (const uint4*)(xl + (size_t)(q0 + tid) * 64);
        #pragma unroll
        for (int k = 0; k < 8; k++) {
            uint32_t off = SMEM_SWIZZLE_128B((uint32_t)(tid * 128 + k * 16));
            *(uint4*)(smem + SM_AHI + off) = sH[k];
            *(uint4*)(smem + SM_ALO + off) = sL[k];
        }
    }
    __syncthreads();

    const int arow = (l & 15);        // ldmatrix x4 lane -> A row within 16
    const int akh  = (l >> 4);        // lane -> A k-half
    const int brow = (l & 7);         // ldmatrix x2 lane -> B row within 8
    const int bkh  = (l >> 3) & 1;    // lane -> B k-half

    // hoisted A fragments: tile-invariant, loaded once (64 registers)
    uint32_t aH[4][2][4], aL[4][2][4];
    #pragma unroll
    for (int ks = 0; ks < 4; ks++) {
        #pragma unroll
        for (int mt = 0; mt < 2; mt++) {
            uint32_t ro = (uint32_t)((w * 32 + mt * 16 + arow) * 128 + ks * 32 + akh * 16);
            uint32_t so = SMEM_SWIZZLE_128B(ro);
            ldsm_x4(aH[ks][mt], sb + SM_AHI + so);
            ldsm_x4(aL[ks][mt], sb + SM_ALO + so);
        }
    }

    float bd[KNNK]; int bi[KNNK];
    #pragma unroll
    for (int i = 0; i < KNNK; i++) { bd[i] = CUDART_INF_F; bi[i] = 0; }

    for (int tile = 0; tile < NPTS / 64; tile++) {
        const int t0 = tile * 64;
        __syncthreads();   // prior scan (reads dist/tnS) done before overwrite
        {
            int r = tid & 63;
            const __nv_bfloat16* src = (tid < 64 ? xh : xl) + (size_t)(t0 + r) * 64;
            char* dstb = smem + (tid < 64 ? SM_BHI : SM_BLO);
            const uint4* s4 = (const uint4*)src;
            #pragma unroll
            for (int k = 0; k < 8; k++) {
                uint32_t off = SMEM_SWIZZLE_128B((uint32_t)(r * 128 + k * 16));
                *(uint4*)(dstb + off) = s4[k];
            }
            if (tid < 64) tnS[tid] = nrm[t0 + tid];
        }
        __syncthreads();

        float acc[2][8][4];
        #pragma unroll
        for (int mt = 0; mt < 2; mt++)
            #pragma unroll
            for (int nt = 0; nt < 8; nt++)
                #pragma unroll
                for (int c = 0; c < 4; c++) acc[mt][nt][c] = 0.f;

        #pragma unroll
        for (int ks = 0; ks < 4; ks++) {
            #pragma unroll
            for (int nt = 0; nt < 8; nt++) {
                uint32_t ro = (uint32_t)((nt * 8 + brow) * 128 + ks * 32 + bkh * 16);
                uint32_t so = SMEM_SWIZZLE_128B(ro);
                uint32_t bH[2], bL[2];
                ldsm_x2(bH, sb + SM_BHI + so);
                ldsm_x2(bL, sb + SM_BLO + so);
                #pragma unroll
                for (int mt = 0; mt < 2; mt++) {
                    mma16816(acc[mt][nt], aH[ks][mt], bH);
                    mma16816(acc[mt][nt], aH[ks][mt], bL);
                    mma16816(acc[mt][nt], aL[ks][mt], bH);
                }
            }
        }

        // stage distances: acc row layout -> dist[query][cand]
        #pragma unroll
        for (int mt = 0; mt < 2; mt++) {
            int r0 = w * 32 + mt * 16 + (l >> 2);
            #pragma unroll
            for (int nt = 0; nt < 8; nt++) {
                int cn = nt * 8 + (l & 3) * 2;
                *(float2*)(dist + (size_t)r0 * 66 + cn) =
                    make_float2(acc[mt][nt][0], acc[mt][nt][1]);
                *(float2*)(dist + (size_t)(r0 + 8) * 66 + cn) =
                    make_float2(acc[mt][nt][2], acc[mt][nt][3]);
            }
        }
        __syncthreads();

        // per-query top-k scan
        const float* drow = dist + (size_t)tid * 66;
        #pragma unroll 8
        for (int j = 0; j < 64; j++) {
            float d = fmaf(-2.f, drow[j], tnS[j]);
            if (d < bd[KNNK - 1]) {
                bd[KNNK - 1] = d; bi[KNNK - 1] = t0 + j;
                #pragma unroll
                for (int s = KNNK - 1; s > 0; s--) {
                    if (bd[s] < bd[s - 1]) {
                        float td = bd[s]; bd[s] = bd[s - 1]; bd[s - 1] = td;
                        int   ti = bi[s]; bi[s] = bi[s - 1]; bi[s - 1] = ti;
                    }
                }
            }
        }
    }

    int* o = idxout + ((size_t)b * NPTS + q0 + tid) * KNNK;
    #pragma unroll
    for (int i = 0; i < KNNK; i++) o[i] = bi[i];
}

// ---------------- edge conv: center-hoisted + dup-packed f32x2 (R5-proven) ----------------
template<int C, bool TWO>
__global__ void edge_conv_kernel(const float* __restrict__ x, const int* __restrict__ knn,
                                 const float* __restrict__ w1, const float* __restrict__ w2,
                                 const float* __restrict__ pa, int ai1, int ai2,
                                 float* __restrict__ out) {
    constexpr int F = 2 * C;
    constexpr int PPB = 16;
    constexpr int WSLOT = 4 * C + (TWO ? 128 : 0);
    extern __shared__ float smf[];
    float* ws1 = smf;
    float* ws2 = ws1 + F * 64;
    float* wsl = ws2 + (TWO ? 4096 : 0);

    int tid = threadIdx.x;
    for (int i = tid; i < F * 64; i += 512) ws1[i] = w1[i];
    if (TWO) for (int i = tid; i < 4096; i += 512) ws2[i] = w2[i];
    float a1 = pa[ai1];
    float a2 = TWO ? pa[ai2] : 0.f;
    __syncthreads();

    int g = tid >> 5, lt = tid & 31;
    size_t pt = (size_t)blockIdx.x * PPB + g;
    int b = (int)(pt / NPTS);
    int n = (int)(pt % NPTS);
    const float* xb = x + (size_t)b * NPTS * C;
    const int* nbr = knn + pt * KNNK;
    float* cdup = wsl + g * WSLOT;
    float* ddup = cdup + 2 * C;
    float* hdup = ddup + 2 * C;

    for (int c = lt; c < C; c += 32) {
        float v = xb[(size_t)n * C + c];
        *(float2*)(cdup + 2 * c) = make_float2(v, v);
    }
    __syncwarp();

    unsigned long long cc = 0ull;
    #pragma unroll 8
    for (int c = 0; c < C; c++) {
        unsigned long long fd = *(const unsigned long long*)(cdup + 2 * c);
        unsigned long long wp = *(const unsigned long long*)(ws1 + (size_t)(C + c) * 64 + 2 * lt);
        cc = fma2(fd, wp, cc);
    }

    float mx0 = -CUDART_INF_F, mx1 = -CUDART_INF_F;
    for (int j = 0; j < KNNK; j++) {
        int nb = nbr[j];
        __syncwarp();
        for (int c = lt; c < C; c += 32) {
            float v = xb[(size_t)nb * C + c] - cdup[2 * c];
            *(float2*)(ddup + 2 * c) = make_float2(v, v);
        }
        __syncwarp();
        unsigned long long acc = cc;
        #pragma unroll 8
        for (int c = 0; c < C; c++) {
            unsigned long long fd = *(const unsigned long long*)(ddup + 2 * c);
            unsigned long long wp = *(const unsigned long long*)(ws1 + (size_t)c * 64 + 2 * lt);
            acc = fma2(fd, wp, acc);
        }
        float s0, s1;
        unpack2(acc, s0, s1);
        float h0  = s0 >= 0.f ? s0 : a1 * s0;
        float hh1 = s1 >= 0.f ? s1 : a1 * s1;
        if (TWO) {
            *(float2*)(hdup + 4 * lt)     = make_float2(h0, h0);
            *(float2*)(hdup + 4 * lt + 2) = make_float2(hh1, hh1);
            __syncwarp();
            unsigned long long acc2 = 0ull;
            #pragma unroll 8
            for (int c = 0; c < 64; c++) {
                unsigned long long fd = *(const unsigned long long*)(hdup + 2 * c);
                unsigned long long wp = *(const unsigned long long*)(ws2 + (size_t)c * 64 + 2 * lt);
                acc2 = fma2(fd, wp, acc2);
            }
            float t0, t1;
            unpack2(acc2, t0, t1);
            h0  = t0 >= 0.f ? t0 : a2 * t0;
            hh1 = t1 >= 0.f ? t1 : a2 * t1;
        }
        mx0 = fmaxf(mx0, h0);
        mx1 = fmaxf(mx1, hh1);
    }
    *(float2*)(out + pt * 64 + 2 * lt) = make_float2(mx0, mx1);
}

// ---------------- concat x4 = [x1|x2|x3] ----------------
__global__ void concat_x4_kernel(const float* __restrict__ x1, const float* __restrict__ x2,
                                 const float* __restrict__ x3, float* __restrict__ x4) {
    int i = blockIdx.x * 256 + threadIdx.x;
    if (i < BATCH * NPTS * 192) {
        int pt = i / 192, c = i % 192;
        float v = (c < 64) ? x1[pt * 64 + c]
                : (c < 128) ? x2[pt * 64 + c - 64]
                : x3[pt * 64 + c - 128];
        x4[i] = v;
    }
}

// ---------------- SGEMM + per-batch bias + PReLU epilogue (R2-proven) ----------------
__global__ void gemm_prelu_kernel(const float* __restrict__ A, const float* __restrict__ B,
                                  float* __restrict__ C, const float* __restrict__ bias,
                                  const float* __restrict__ pa, int aidx,
                                  int K, int Nc) {
    __shared__ float As[16][64];
    __shared__ float Bs[16][64];
    int tid = threadIdx.x;
    int tx = tid & 15, ty = tid >> 4;
    int m0 = blockIdx.x * 64, n0 = blockIdx.y * 64;

    float acc[8][4];
    #pragma unroll
    for (int r = 0; r < 8; r++)
        #pragma unroll
        for (int c = 0; c < 4; c++) acc[r][c] = 0.f;

    for (int k0 = 0; k0 < K; k0 += 16) {
        #pragma unroll
        for (int l = 0; l < 2; l++) {
            int i = tid * 2 + l;
            int m = i >> 2, kc = (i & 3) * 4;
            float4 v = *(const float4*)(A + (size_t)(m0 + m) * K + k0 + kc);
            As[kc + 0][m] = v.x; As[kc + 1][m] = v.y;
            As[kc + 2][m] = v.z; As[kc + 3][m] = v.w;
            int kb = i >> 4, nb = (i & 15) * 4;
            float4 w = *(const float4*)(B + (size_t)(k0 + kb) * Nc + n0 + nb);
            *(float4*)(&Bs[kb][nb]) = w;
        }
        __syncthreads();
        #pragma unroll
        for (int kk = 0; kk < 16; kk++) {
            float a[8], bb[4];
            #pragma unroll
            for (int r = 0; r < 8; r++) a[r] = As[kk][ty * 8 + r];
            #pragma unroll
            for (int c = 0; c < 4; c++) bb[c] = Bs[kk][tx * 4 + c];
            #pragma unroll
            for (int r = 0; r < 8; r++)
                #pragma unroll
                for (int c = 0; c < 4; c++)
                    acc[r][c] = fmaf(a[r], bb[c], acc[r][c]);
        }
        __syncthreads();
    }

    float al = pa[aidx];
    #pragma unroll
    for (int r = 0; r < 8; r++) {
        size_t m = (size_t)m0 + ty * 8 + r;
        int n = n0 + tx * 4;
        float4 v;
        float bv0 = 0.f, bv1 = 0.f, bv2 = 0.f, bv3 = 0.f;
        if (bias) {
            const float* brow = bias + (m >> 13) * Nc;
            bv0 = brow[n]; bv1 = brow[n + 1]; bv2 = brow[n + 2]; bv3 = brow[n + 3];
        }
        float e0 = acc[r][0] + bv0, e1 = acc[r][1] + bv1;
        float e2 = acc[r][2] + bv2, e3 = acc[r][3] + bv3;
        v.x = e0 >= 0.f ? e0 : al * e0;
        v.y = e1 >= 0.f ? e1 : al * e1;
        v.z = e2 >= 0.f ? e2 : al * e2;
        v.w = e3 >= 0.f ? e3 : al * e3;
        *(float4*)(C + m * Nc + n) = v;
    }
}

// ---------------- global max over N + bias from w7 tail ----------------
__global__ void max1_kernel(const float* __restrict__ x5, float* __restrict__ pmax) {
    int b = blockIdx.y, chunk = blockIdx.x, c = threadIdx.x;
    const float* p = x5 + ((size_t)b * NPTS + (size_t)chunk * 256) * 1024 + c;
    float m = -CUDART_INF_F;
    for (int n = 0; n < 256; n++) m = fmaxf(m, p[(size_t)n * 1024]);
    pmax[((size_t)b * 32 + chunk) * 1024 + c] = m;
}
__global__ void max2_kernel(const float* __restrict__ pmax, float* __restrict__ x5max) {
    int b = blockIdx.x, c = threadIdx.x;
    float m = -CUDART_INF_F;
    for (int k = 0; k < 32; k++) m = fmaxf(m, pmax[((size_t)b * 32 + k) * 1024 + c]);
    x5max[b * 1024 + c] = m;
}
__global__ void bias_kernel(const float* __restrict__ x5max, const float* __restrict__ w7,
                            float* __restrict__ bias) {
    int b = blockIdx.x, j = threadIdx.x;
    float s = 0.f;
    for (int c = 0; c < 1024; c++)
        s = fmaf(x5max[b * 1024 + c], w7[(size_t)(192 + c) * 256 + j], s);
    bias[b * 256 + j] = s;
}

// ---------------- final 128->2 layer ----------------
__global__ void final_kernel(const float* __restrict__ y3, const float* __restrict__ w10,
                             const float* __restrict__ pa, float* __restrict__ out) {
    __shared__ float ws[256];
    int tid = threadIdx.x;
    ws[tid * 2] = w10[tid * 2];
    ws[tid * 2 + 1] = w10[tid * 2 + 1];
    __syncthreads();
    int warp = tid >> 5, lane = tid & 31;
    size_t pt = (size_t)blockIdx.x * 4 + warp;
    const float* row = y3 + pt * 128;
    float s0 = 0.f, s1 = 0.f;
    for (int c = lane; c < 128; c += 32) {
        float v = row[c];
        s0 = fmaf(v, ws[c * 2], s0);
        s1 = fmaf(v, ws[c * 2 + 1], s1);
    }
    #pragma unroll
    for (int o = 16; o > 0; o >>= 1) {
        s0 += __shfl_down_sync(0xffffffffu, s0, o);
        s1 += __shfl_down_sync(0xffffffffu, s1, o);
    }
    if (lane == 0) {
        float a = pa[9];
        out[pt * 2]     = s0 >= 0.f ? s0 : a * s0;
        out[pt * 2 + 1] = s1 >= 0.f ? s1 : a * s1;
    }
}

// ---------------- host orchestration ----------------
extern "C" void kernel_launch(void* const* d_in, const int* in_sizes, int n_in,
                              void* d_out, int out_size) {
    const float* targets = (const float*)d_in[0];
    const float* w[10];
    for (int i = 0; i < 10; i++) w[i] = (const float*)d_in[1 + i];
    const float* pa = (const float*)d_in[11];
    float* out = (float*)d_out;

    float* base = nullptr;
    cudaGetSymbolAddress((void**)&base, g_scratch);
    float* x0    = base + O_X0;
    int*   idx   = (int*)(base + O_IDX);
    float* x1    = base + O_X1;
    float* x2    = base + O_X2;
    float* x3    = base + O_X3;
    float* x4    = base + O_X4;
    float* x5    = base + O_X5;
    float* pmax  = base + O_PMAX;
    float* x5max = base + O_X5MAX;
    float* bias  = base + O_BIAS;
    float* y1    = base + O_Y1;
    float* y2    = base + O_Y2;
    float* y3    = base + O_Y3;
    __nv_bfloat16* xhi = (__nv_bfloat16*)(base + O_XHI);
    __nv_bfloat16* xlo = (__nv_bfloat16*)(base + O_XLO);
    float* nrm   = base + O_NORM;

    const int smem6t  = (12 * 64 + 4096 + 16 * (4 * 6 + 128)) * 4;
    const int smem64t = (128 * 64 + 4096 + 16 * (4 * 64 + 128)) * 4;
    const int smem64f = (128 * 64 + 16 * (4 * 64)) * 4;

    cudaFuncSetAttribute(edge_conv_kernel<64, true>,
                         cudaFuncAttributeMaxDynamicSharedMemorySize, smem64t);
    cudaFuncSetAttribute(edge_conv_kernel<64, false>,
                         cudaFuncAttributeMaxDynamicSharedMemorySize, smem64f);
    cudaFuncSetAttribute(knn_mma_kernel,
                         cudaFuncAttributeMaxDynamicSharedMemorySize, SM_KNN_TOTAL);

    const int NCVT = BATCH * NPTS * 64;

    build_x0_kernel<<<(BATCH * NPTS * 6 + 255) / 256, 256>>>(targets, x0);

    knn_kernel<6><<<dim3(NPTS / 128, BATCH), 128>>>(x0, idx);
    edge_conv_kernel<6, true><<<BATCH * NPTS / 16, 512, smem6t>>>(x0, idx, w[0], w[1], pa, 0, 1, x1);

    cvt_split_kernel<<<(NCVT + 255) / 256, 256>>>(x1, xhi, xlo, NCVT);
    norms_kernel<<<(BATCH * NPTS + 255) / 256, 256>>>(x1, nrm);
    knn_mma_kernel<<<dim3(NPTS / 128, BATCH), 128, SM_KNN_TOTAL>>>(xhi, xlo, nrm, idx);
    edge_conv_kernel<64, true><<<BATCH * NPTS / 16, 512, smem64t>>>(x1, idx, w[2], w[3], pa, 2, 3, x2);

    cvt_split_kernel<<<(NCVT + 255) / 256, 256>>>(x2, xhi, xlo, NCVT);
    norms_kernel<<<(BATCH * NPTS + 255) / 256, 256>>>(x2, nrm);
    knn_mma_kernel<<<dim3(NPTS / 128, BATCH), 128, SM_KNN_TOTAL>>>(xhi, xlo, nrm, idx);
    edge_conv_kernel<64, false><<<BATCH * NPTS / 16, 512, smem64f>>>(x2, idx, w[4], nullptr, pa, 4, 4, x3);

    concat_x4_kernel<<<(BATCH * NPTS * 192 + 255) / 256, 256>>>(x1, x2, x3, x4);

    gemm_prelu_kernel<<<dim3(BATCH * NPTS / 64, 1024 / 64), 128>>>(x4, w[5], x5, nullptr, pa, 5, 192, 1024);
    max1_kernel<<<dim3(32, BATCH), 1024>>>(x5, pmax);
    max2_kernel<<<BATCH, 1024>>>(pmax, x5max);
    bias_kernel<<<BATCH, 256>>>(x5max, w[6], bias);

    gemm_prelu_kernel<<<dim3(BATCH * NPTS / 64, 256 / 64), 128>>>(x4, w[6], y1, bias, pa, 6, 192, 256);
    gemm_prelu_kernel<<<dim3(BATCH * NPTS / 64, 256 / 64), 128>>>(y1, w[7], y2, nullptr, pa, 7, 256, 256);
    gemm_prelu_kernel<<<dim3(BATCH * NPTS / 64, 128 / 64), 128>>>(y2, w[8], y3, nullptr, pa, 8, 256, 128);
    final_kernel<<<BATCH * NPTS / 4, 128>>>(y3, w[9], pa, out);

    (void)in_sizes; (void)n_in; (void)out_size;
}

// round 13
// speedup vs baseline: 1.5872x; 1.5872x over previous
#include <cuda_runtime.h>
#include <cuda_bf16.h>
#include <math_constants.h>
#include <cstdint>

#define NPTS 8192
#define BATCH 4
#define KNNK 10
#define NSPLIT6 4
#define SPLITLEN6 (NPTS / NSPLIT6)

// ---------------- scratch arena (no allocation allowed) ----------------
#define O_X0     0u
#define O_IDX    196608u
#define O_X1     524288u
#define O_X2     2621440u
#define O_X3     4718592u
#define O_X4     6815744u
#define O_X5     13107200u
#define O_PMAX   46661632u
#define O_X5MAX  46792704u
#define O_BIAS   46796800u
#define O_Y1     46797824u
#define O_Y2     55186432u
#define O_Y3     63575040u
#define O_XHI    67769344u   // 2,097,152 bf16 = 1,048,576 floats
#define O_XLO    68817920u
#define O_NORM   69866496u   // 32768 floats
#define O_SD     69899264u   // 4*8192*4*10 = 1,310,720 floats
#define O_SI     71209984u   // 1,310,720 ints
#define SCRATCH_FLOATS 72520704u

__device__ __align__(16) float g_scratch[SCRATCH_FLOATS];

// ---------------- f32x2 packed helpers (sm_103a) ----------------
__device__ __forceinline__ void unpack2(unsigned long long v, float& lo, float& hi) {
    asm("mov.b64 {%0, %1}, %2;" : "=f"(lo), "=f"(hi) : "l"(v));
}
__device__ __forceinline__ unsigned long long fma2(unsigned long long a,
                                                   unsigned long long b,
                                                   unsigned long long c) {
    unsigned long long d;
    asm("fma.rn.f32x2 %0, %1, %2, %3;" : "=l"(d) : "l"(a), "l"(b), "l"(c));
    return d;
}

// ---------------- warp-mma helpers (target-independent PTX) ----------------
__device__ __forceinline__ uint32_t smem_to_u32(const void* p) {
    uint32_t a;
    asm("{ .reg .u64 t; cvta.to.shared.u64 t, %1; cvt.u32.u64 %0, t; }" : "=r"(a) : "l"(p));
    return a;
}
#define SMEM_SWIZZLE_128B(o) ((o) ^ (((o) >> 3) & 0x70))

__device__ __forceinline__ void ldsm_x4(uint32_t a[4], uint32_t addr) {
    asm volatile("ldmatrix.sync.aligned.m8n8.x4.shared.b16 {%0,%1,%2,%3}, [%4];"
        : "=r"(a[0]), "=r"(a[1]), "=r"(a[2]), "=r"(a[3]) : "r"(addr));
}
__device__ __forceinline__ void ldsm_x2(uint32_t a[2], uint32_t addr) {
    asm volatile("ldmatrix.sync.aligned.m8n8.x2.shared.b16 {%0,%1}, [%2];"
        : "=r"(a[0]), "=r"(a[1]) : "r"(addr));
}
__device__ __forceinline__ void mma16816(float c[4], const uint32_t a[4], const uint32_t b[2]) {
    asm volatile("mma.sync.aligned.m16n8k16.row.col.f32.bf16.bf16.f32 "
        "{%0,%1,%2,%3}, {%4,%5,%6,%7}, {%8,%9}, {%0,%1,%2,%3};"
        : "+f"(c[0]), "+f"(c[1]), "+f"(c[2]), "+f"(c[3])
        : "r"(a[0]), "r"(a[1]), "r"(a[2]), "r"(a[3]), "r"(b[0]), "r"(b[1]));
}

// ---------------- build x0 = concat(targets, targets) ----------------
__global__ void build_x0_kernel(const float* __restrict__ t, float* __restrict__ x0) {
    int i = blockIdx.x * blockDim.x + threadIdx.x;
    if (i < BATCH * NPTS * 6) {
        int pt = i / 6, c = i % 6;
        x0[i] = t[pt * 3 + (c < 3 ? c : c - 3)];
    }
}

// ---------------- fused fp32 -> bf16 hi/lo split + squared norm (warp/point) ----------------
__global__ void cvt_norm_kernel(const float* __restrict__ x,
                                __nv_bfloat16* __restrict__ hi,
                                __nv_bfloat16* __restrict__ lo,
                                float* __restrict__ norms) {
    int gw = (blockIdx.x * 256 + threadIdx.x) >> 5;   // warp = point
    int lane = threadIdx.x & 31;
    if (gw >= BATCH * NPTS) return;
    float2 v = *(const float2*)(x + (size_t)gw * 64 + lane * 2);
    __nv_bfloat16 h0 = __float2bfloat16(v.x);
    __nv_bfloat16 h1 = __float2bfloat16(v.y);
    __nv_bfloat16 l0 = __float2bfloat16(v.x - __bfloat162float(h0));
    __nv_bfloat16 l1 = __float2bfloat16(v.y - __bfloat162float(h1));
    *(__nv_bfloat162*)(hi + (size_t)gw * 64 + lane * 2) = __nv_bfloat162(h0, h1);
    *(__nv_bfloat162*)(lo + (size_t)gw * 64 + lane * 2) = __nv_bfloat162(l0, l1);
    float s = fmaf(v.x, v.x, v.y * v.y);
    #pragma unroll
    for (int o = 16; o > 0; o >>= 1) s += __shfl_down_sync(0xffffffffu, s, o);
    if (lane == 0) norms[gw] = s;
}

// ---------------- KNN C=6: candidate-split (R4-proven pattern, scalar C=6) ----------------
// grid (NPTS/128, NSPLIT6, BATCH), block 128, thread per query.
__global__ void knn6_split_kernel(const float* __restrict__ x,
                                  float* __restrict__ sd, int* __restrict__ si) {
    __shared__ float tile[128 * 6];
    __shared__ float tnorm[128];
    const int b = blockIdx.z;
    const int sp = blockIdx.y;
    const int q = blockIdx.x * 128 + threadIdx.x;
    const float* xb = x + (size_t)b * NPTS * 6;
    const int cand0 = sp * SPLITLEN6;

    float qf[6];
    float qn = 0.f;
    #pragma unroll
    for (int c = 0; c < 6; c++) { qf[c] = xb[q * 6 + c]; qn = fmaf(qf[c], qf[c], qn); }

    float bd[KNNK]; int bi[KNNK];
    #pragma unroll
    for (int i = 0; i < KNNK; i++) { bd[i] = CUDART_INF_F; bi[i] = 0; }

    for (int t0 = cand0; t0 < cand0 + SPLITLEN6; t0 += 128) {
        __syncthreads();
        for (int i = threadIdx.x; i < 128 * 6; i += 128) tile[i] = xb[t0 * 6 + i];
        __syncthreads();
        {
            float s = 0.f;
            #pragma unroll
            for (int c = 0; c < 6; c++) {
                float v = tile[threadIdx.x * 6 + c];
                s = fmaf(v, v, s);
            }
            tnorm[threadIdx.x] = s;
        }
        __syncthreads();
        for (int j = 0; j < 128; j++) {
            float d0 = 0.f, d1 = 0.f;
            #pragma unroll
            for (int c = 0; c < 6; c += 2) {
                d0 = fmaf(qf[c + 0], tile[j * 6 + c + 0], d0);
                d1 = fmaf(qf[c + 1], tile[j * 6 + c + 1], d1);
            }
            float d = qn + tnorm[j] - 2.f * (d0 + d1);
            if (d < bd[KNNK - 1]) {
                bd[KNNK - 1] = d; bi[KNNK - 1] = t0 + j;
                #pragma unroll
                for (int s = KNNK - 1; s > 0; s--) {
                    if (bd[s] < bd[s - 1]) {
                        float td = bd[s]; bd[s] = bd[s - 1]; bd[s - 1] = td;
                        int   ti = bi[s]; bi[s] = bi[s - 1]; bi[s - 1] = ti;
                    }
                }
            }
        }
    }
    size_t o = (((size_t)b * NPTS + q) * NSPLIT6 + sp) * KNNK;
    #pragma unroll
    for (int i = 0; i < KNNK; i++) { sd[o + i] = bd[i]; si[o + i] = bi[i]; }
}

// merge NSPLIT6 partial top-10 lists into final indices (R4-proven)
__global__ void knn_merge_kernel(const float* __restrict__ sd, const int* __restrict__ si,
                                 int* __restrict__ idxout) {
    int p = blockIdx.x * 256 + threadIdx.x;
    if (p >= BATCH * NPTS) return;
    const float* d = sd + (size_t)p * NSPLIT6 * KNNK;
    const int* ix = si + (size_t)p * NSPLIT6 * KNNK;
    float bd[KNNK]; int bi[KNNK];
    #pragma unroll
    for (int i = 0; i < KNNK; i++) { bd[i] = CUDART_INF_F; bi[i] = 0; }
    #pragma unroll 4
    for (int s = 0; s < NSPLIT6 * KNNK; s++) {
        float dv = d[s];
        if (dv < bd[KNNK - 1]) {
            bd[KNNK - 1] = dv; bi[KNNK - 1] = ix[s];
            #pragma unroll
            for (int t = KNNK - 1; t > 0; t--) {
                if (bd[t] < bd[t - 1]) {
                    float td = bd[t]; bd[t] = bd[t - 1]; bd[t - 1] = td;
                    int   ti = bi[t]; bi[t] = bi[t - 1]; bi[t - 1] = ti;
                }
            }
        }
    }
    int* o = idxout + (size_t)p * KNNK;
    #pragma unroll
    for (int i = 0; i < KNNK; i++) o[i] = bi[i];
}

// ---------------- KNN C=64 on tensor cores (R8-proven, byte-identical) ----------------
// block 128 threads = 4 warps; block owns 128 queries; 128 candidate tiles of 64.
// dot = Ahi@Bhi^T + Ahi@Blo^T + Alo@Bhi^T ; d = |x_j|^2 - 2*dot (ordering exact).
#define SM_AHI   0          // 128 rows x 128B (SW128)
#define SM_ALO   16384
#define SM_BHI   32768      // 64 rows x 128B
#define SM_BLO   40960
#define SM_TN    49152      // 64 floats
#define SM_DIST  49408      // 128 x 66 floats
#define SM_KNN_TOTAL 83200

__global__ __launch_bounds__(128)
void knn_mma_kernel(const __nv_bfloat16* __restrict__ xhi,
                    const __nv_bfloat16* __restrict__ xlo,
                    const float* __restrict__ norms,
                    int* __restrict__ idxout) {
    extern __shared__ char smem[];
    const uint32_t sb = smem_to_u32(smem);
    float* tnS  = (float*)(smem + SM_TN);
    float* dist = (float*)(smem + SM_DIST);
    const int tid = threadIdx.x, w = tid >> 5, l = tid & 31;
    const int b = blockIdx.y, q0 = blockIdx.x * 128;
    const __nv_bfloat16* xh = xhi + (size_t)b * NPTS * 64;
    const __nv_bfloat16* xl = xlo + (size_t)b * NPTS * 64;
    const float* nrm = norms + (size_t)b * NPTS;

    // A tiles (queries), SW128 swizzled; row = 64 bf16 = 128B.
    {
        const uint4* sH = (const uint4*)(xh + (size_t)(q0 + tid) * 64);
        const uint4* sL = (const uint4*)(xl + (size_t)(q0 + tid) * 64);
        #pragma unroll
        for (int k = 0; k < 8; k++) {
            uint32_t off = SMEM_SWIZZLE_128B((uint32_t)(tid * 128 + k * 16));
            *(uint4*)(smem + SM_AHI + off) = sH[k];
            *(uint4*)(smem + SM_ALO + off) = sL[k];
        }
    }

    float bd[KNNK]; int bi[KNNK];
    #pragma unroll
    for (int i = 0; i < KNNK; i++) { bd[i] = CUDART_INF_F; bi[i] = 0; }

    const int arow = (l & 15);        // ldmatrix x4 lane -> A row within 16
    const int akh  = (l >> 4);        // lane -> A k-half
    const int brow = (l & 7);         // ldmatrix x2 lane -> B row within 8
    const int bkh  = (l >> 3) & 1;    // lane -> B k-half

    for (int tile = 0; tile < NPTS / 64; tile++) {
        const int t0 = tile * 64;
        __syncthreads();   // prior scan (reads dist/tnS) done before overwrite
        {
            int r = tid & 63;
            const __nv_bfloat16* src = (tid < 64 ? xh : xl) + (size_t)(t0 + r) * 64;
            char* dstb = smem + (tid < 64 ? SM_BHI : SM_BLO);
            const uint4* s4 = (const uint4*)src;
            #pragma unroll
            for (int k = 0; k < 8; k++) {
                uint32_t off = SMEM_SWIZZLE_128B((uint32_t)(r * 128 + k * 16));
                *(uint4*)(dstb + off) = s4[k];
            }
            if (tid < 64) tnS[tid] = nrm[t0 + tid];
        }
        __syncthreads();

        float acc[2][8][4];
        #pragma unroll
        for (int mt = 0; mt < 2; mt++)
            #pragma unroll
            for (int nt = 0; nt < 8; nt++)
                #pragma unroll
                for (int c = 0; c < 4; c++) acc[mt][nt][c] = 0.f;

        #pragma unroll
        for (int ks = 0; ks < 4; ks++) {
            uint32_t aH[2][4], aL[2][4];
            #pragma unroll
            for (int mt = 0; mt < 2; mt++) {
                uint32_t ro = (uint32_t)((w * 32 + mt * 16 + arow) * 128 + ks * 32 + akh * 16);
                uint32_t so = SMEM_SWIZZLE_128B(ro);
                ldsm_x4(aH[mt], sb + SM_AHI + so);
                ldsm_x4(aL[mt], sb + SM_ALO + so);
            }
            #pragma unroll
            for (int nt = 0; nt < 8; nt++) {
                uint32_t ro = (uint32_t)((nt * 8 + brow) * 128 + ks * 32 + bkh * 16);
                uint32_t so = SMEM_SWIZZLE_128B(ro);
                uint32_t bH[2], bL[2];
                ldsm_x2(bH, sb + SM_BHI + so);
                ldsm_x2(bL, sb + SM_BLO + so);
                #pragma unroll
                for (int mt = 0; mt < 2; mt++) {
                    mma16816(acc[mt][nt], aH[mt], bH);
                    mma16816(acc[mt][nt], aH[mt], bL);
                    mma16816(acc[mt][nt], aL[mt], bH);
                }
            }
        }

        // stage distances: acc row layout -> dist[query][cand]
        #pragma unroll
        for (int mt = 0; mt < 2; mt++) {
            int r0 = w * 32 + mt * 16 + (l >> 2);
            #pragma unroll
            for (int nt = 0; nt < 8; nt++) {
                int cn = nt * 8 + (l & 3) * 2;
                *(float2*)(dist + (size_t)r0 * 66 + cn) =
                    make_float2(acc[mt][nt][0], acc[mt][nt][1]);
                *(float2*)(dist + (size_t)(r0 + 8) * 66 + cn) =
                    make_float2(acc[mt][nt][2], acc[mt][nt][3]);
            }
        }
        __syncthreads();

        // per-query top-k scan
        const float* drow = dist + (size_t)tid * 66;
        #pragma unroll 8
        for (int j = 0; j < 64; j++) {
            float d = fmaf(-2.f, drow[j], tnS[j]);
            if (d < bd[KNNK - 1]) {
                bd[KNNK - 1] = d; bi[KNNK - 1] = t0 + j;
                #pragma unroll
                for (int s = KNNK - 1; s > 0; s--) {
                    if (bd[s] < bd[s - 1]) {
                        float td = bd[s]; bd[s] = bd[s - 1]; bd[s - 1] = td;
                        int   ti = bi[s]; bi[s] = bi[s - 1]; bi[s - 1] = ti;
                    }
                }
            }
        }
    }

    int* o = idxout + ((size_t)b * NPTS + q0 + tid) * KNNK;
    #pragma unroll
    for (int i = 0; i < KNNK; i++) o[i] = bi[i];
}

// ---------------- edge conv: center-hoisted + dup-packed f32x2 (R5-proven) ----------------
template<int C, bool TWO>
__global__ void edge_conv_kernel(const float* __restrict__ x, const int* __restrict__ knn,
                                 const float* __restrict__ w1, const float* __restrict__ w2,
                                 const float* __restrict__ pa, int ai1, int ai2,
                                 float* __restrict__ out) {
    constexpr int F = 2 * C;
    constexpr int PPB = 16;
    constexpr int WSLOT = 4 * C + (TWO ? 128 : 0);
    extern __shared__ float smf[];
    float* ws1 = smf;
    float* ws2 = ws1 + F * 64;
    float* wsl = ws2 + (TWO ? 4096 : 0);

    int tid = threadIdx.x;
    for (int i = tid; i < F * 64; i += 512) ws1[i] = w1[i];
    if (TWO) for (int i = tid; i < 4096; i += 512) ws2[i] = w2[i];
    float a1 = pa[ai1];
    float a2 = TWO ? pa[ai2] : 0.f;
    __syncthreads();

    int g = tid >> 5, lt = tid & 31;
    size_t pt = (size_t)blockIdx.x * PPB + g;
    int b = (int)(pt / NPTS);
    int n = (int)(pt % NPTS);
    const float* xb = x + (size_t)b * NPTS * C;
    const int* nbr = knn + pt * KNNK;
    float* cdup = wsl + g * WSLOT;
    float* ddup = cdup + 2 * C;
    float* hdup = ddup + 2 * C;

    for (int c = lt; c < C; c += 32) {
        float v = xb[(size_t)n * C + c];
        *(float2*)(cdup + 2 * c) = make_float2(v, v);
    }
    __syncwarp();

    unsigned long long cc = 0ull;
    #pragma unroll 8
    for (int c = 0; c < C; c++) {
        unsigned long long fd = *(const unsigned long long*)(cdup + 2 * c);
        unsigned long long wp = *(const unsigned long long*)(ws1 + (size_t)(C + c) * 64 + 2 * lt);
        cc = fma2(fd, wp, cc);
    }

    float mx0 = -CUDART_INF_F, mx1 = -CUDART_INF_F;
    for (int j = 0; j < KNNK; j++) {
        int nb = nbr[j];
        __syncwarp();
        for (int c = lt; c < C; c += 32) {
            float v = xb[(size_t)nb * C + c] - cdup[2 * c];
            *(float2*)(ddup + 2 * c) = make_float2(v, v);
        }
        __syncwarp();
        unsigned long long acc = cc;
        #pragma unroll 8
        for (int c = 0; c < C; c++) {
            unsigned long long fd = *(const unsigned long long*)(ddup + 2 * c);
            unsigned long long wp = *(const unsigned long long*)(ws1 + (size_t)c * 64 + 2 * lt);
            acc = fma2(fd, wp, acc);
        }
        float s0, s1;
        unpack2(acc, s0, s1);
        float h0  = s0 >= 0.f ? s0 : a1 * s0;
        float hh1 = s1 >= 0.f ? s1 : a1 * s1;
        if (TWO) {
            *(float2*)(hdup + 4 * lt)     = make_float2(h0, h0);
            *(float2*)(hdup + 4 * lt + 2) = make_float2(hh1, hh1);
            __syncwarp();
            unsigned long long acc2 = 0ull;
            #pragma unroll 8
            for (int c = 0; c < 64; c++) {
                unsigned long long fd = *(const unsigned long long*)(hdup + 2 * c);
                unsigned long long wp = *(const unsigned long long*)(ws2 + (size_t)c * 64 + 2 * lt);
                acc2 = fma2(fd, wp, acc2);
            }
            float t0, t1;
            unpack2(acc2, t0, t1);
            h0  = t0 >= 0.f ? t0 : a2 * t0;
            hh1 = t1 >= 0.f ? t1 : a2 * t1;
        }
        mx0 = fmaxf(mx0, h0);
        mx1 = fmaxf(mx1, hh1);
    }
    *(float2*)(out + pt * 64 + 2 * lt) = make_float2(mx0, mx1);
}

// ---------------- concat x4 = [x1|x2|x3] ----------------
__global__ void concat_x4_kernel(const float* __restrict__ x1, const float* __restrict__ x2,
                                 const float* __restrict__ x3, float* __restrict__ x4) {
    int i = blockIdx.x * 256 + threadIdx.x;
    if (i < BATCH * NPTS * 192) {
        int pt = i / 192, c = i % 192;
        float v = (c < 64) ? x1[pt * 64 + c]
                : (c < 128) ? x2[pt * 64 + c - 64]
                : x3[pt * 64 + c - 128];
        x4[i] = v;
    }
}

// ---------------- SGEMM + per-batch bias + PReLU epilogue (R2-proven) ----------------
__global__ void gemm_prelu_kernel(const float* __restrict__ A, const float* __restrict__ B,
                                  float* __restrict__ C, const float* __restrict__ bias,
                                  const float* __restrict__ pa, int aidx,
                                  int K, int Nc) {
    __shared__ float As[16][64];
    __shared__ float Bs[16][64];
    int tid = threadIdx.x;
    int tx = tid & 15, ty = tid >> 4;
    int m0 = blockIdx.x * 64, n0 = blockIdx.y * 64;

    float acc[8][4];
    #pragma unroll
    for (int r = 0; r < 8; r++)
        #pragma unroll
        for (int c = 0; c < 4; c++) acc[r][c] = 0.f;

    for (int k0 = 0; k0 < K; k0 += 16) {
        #pragma unroll
        for (int l = 0; l < 2; l++) {
            int i = tid * 2 + l;
            int m = i >> 2, kc = (i & 3) * 4;
            float4 v = *(const float4*)(A + (size_t)(m0 + m) * K + k0 + kc);
            As[kc + 0][m] = v.x; As[kc + 1][m] = v.y;
            As[kc + 2][m] = v.z; As[kc + 3][m] = v.w;
            int kb = i >> 4, nb = (i & 15) * 4;
            float4 w = *(const float4*)(B + (size_t)(k0 + kb) * Nc + n0 + nb);
            *(float4*)(&Bs[kb][nb]) = w;
        }
        __syncthreads();
        #pragma unroll
        for (int kk = 0; kk < 16; kk++) {
            float a[8], bb[4];
            #pragma unroll
            for (int r = 0; r < 8; r++) a[r] = As[kk][ty * 8 + r];
            #pragma unroll
            for (int c = 0; c < 4; c++) bb[c] = Bs[kk][tx * 4 + c];
            #pragma unroll
            for (int r = 0; r < 8; r++)
                #pragma unroll
                for (int c = 0; c < 4; c++)
                    acc[r][c] = fmaf(a[r], bb[c], acc[r][c]);
        }
        __syncthreads();
    }

    float al = pa[aidx];
    #pragma unroll
    for (int r = 0; r < 8; r++) {
        size_t m = (size_t)m0 + ty * 8 + r;
        int n = n0 + tx * 4;
        float4 v;
        float bv0 = 0.f, bv1 = 0.f, bv2 = 0.f, bv3 = 0.f;
        if (bias) {
            const float* brow = bias + (m >> 13) * Nc;
            bv0 = brow[n]; bv1 = brow[n + 1]; bv2 = brow[n + 2]; bv3 = brow[n + 3];
        }
        float e0 = acc[r][0] + bv0, e1 = acc[r][1] + bv1;
        float e2 = acc[r][2] + bv2, e3 = acc[r][3] + bv3;
        v.x = e0 >= 0.f ? e0 : al * e0;
        v.y = e1 >= 0.f ? e1 : al * e1;
        v.z = e2 >= 0.f ? e2 : al * e2;
        v.w = e3 >= 0.f ? e3 : al * e3;
        *(float4*)(C + m * Nc + n) = v;
    }
}

// ---------------- global max over N + bias from w7 tail ----------------
__global__ void max1_kernel(const float* __restrict__ x5, float* __restrict__ pmax) {
    int b = blockIdx.y, chunk = blockIdx.x, c = threadIdx.x;
    const float* p = x5 + ((size_t)b * NPTS + (size_t)chunk * 256) * 1024 + c;
    float m = -CUDART_INF_F;
    for (int n = 0; n < 256; n++) m = fmaxf(m, p[(size_t)n * 1024]);
    pmax[((size_t)b * 32 + chunk) * 1024 + c] = m;
}
__global__ void max2_kernel(const float* __restrict__ pmax, float* __restrict__ x5max) {
    int b = blockIdx.x, c = threadIdx.x;
    float m = -CUDART_INF_F;
    for (int k = 0; k < 32; k++) m = fmaxf(m, pmax[((size_t)b * 32 + k) * 1024 + c]);
    x5max[b * 1024 + c] = m;
}
__global__ void bias_kernel(const float* __restrict__ x5max, const float* __restrict__ w7,
                            float* __restrict__ bias) {
    int b = blockIdx.x, j = threadIdx.x;
    float s = 0.f;
    for (int c = 0; c < 1024; c++)
        s = fmaf(x5max[b * 1024 + c], w7[(size_t)(192 + c) * 256 + j], s);
    bias[b * 256 + j] = s;
}

// ---------------- final 128->2 layer ----------------
__global__ void final_kernel(const float* __restrict__ y3, const float* __restrict__ w10,
                             const float* __restrict__ pa, float* __restrict__ out) {
    __shared__ float ws[256];
    int tid = threadIdx.x;
    ws[tid * 2] = w10[tid * 2];
    ws[tid * 2 + 1] = w10[tid * 2 + 1];
    __syncthreads();
    int warp = tid >> 5, lane = tid & 31;
    size_t pt = (size_t)blockIdx.x * 4 + warp;
    const float* row = y3 + pt * 128;
    float s0 = 0.f, s1 = 0.f;
    for (int c = lane; c < 128; c += 32) {
        float v = row[c];
        s0 = fmaf(v, ws[c * 2], s0);
        s1 = fmaf(v, ws[c * 2 + 1], s1);
    }
    #pragma unroll
    for (int o = 16; o > 0; o >>= 1) {
        s0 += __shfl_down_sync(0xffffffffu, s0, o);
        s1 += __shfl_down_sync(0xffffffffu, s1, o);
    }
    if (lane == 0) {
        float a = pa[9];
        out[pt * 2]     = s0 >= 0.f ? s0 : a * s0;
        out[pt * 2 + 1] = s1 >= 0.f ? s1 : a * s1;
    }
}

// ---------------- host orchestration ----------------
extern "C" void kernel_launch(void* const* d_in, const int* in_sizes, int n_in,
                              void* d_out, int out_size) {
    const float* targets = (const float*)d_in[0];
    const float* w[10];
    for (int i = 0; i < 10; i++) w[i] = (const float*)d_in[1 + i];
    const float* pa = (const float*)d_in[11];
    float* out = (float*)d_out;

    float* base = nullptr;
    cudaGetSymbolAddress((void**)&base, g_scratch);
    float* x0    = base + O_X0;
    int*   idx   = (int*)(base + O_IDX);
    float* x1    = base + O_X1;
    float* x2    = base + O_X2;
    float* x3    = base + O_X3;
    float* x4    = base + O_X4;
    float* x5    = base + O_X5;
    float* pmax  = base + O_PMAX;
    float* x5max = base + O_X5MAX;
    float* bias  = base + O_BIAS;
    float* y1    = base + O_Y1;
    float* y2    = base + O_Y2;
    float* y3    = base + O_Y3;
    __nv_bfloat16* xhi = (__nv_bfloat16*)(base + O_XHI);
    __nv_bfloat16* xlo = (__nv_bfloat16*)(base + O_XLO);
    float* nrm   = base + O_NORM;
    float* sd    = base + O_SD;
    int*   si    = (int*)(base + O_SI);

    const int smem6t  = (12 * 64 + 4096 + 16 * (4 * 6 + 128)) * 4;
    const int smem64t = (128 * 64 + 4096 + 16 * (4 * 64 + 128)) * 4;
    const int smem64f = (128 * 64 + 16 * (4 * 64)) * 4;

    cudaFuncSetAttribute(edge_conv_kernel<64, true>,
                         cudaFuncAttributeMaxDynamicSharedMemorySize, smem64t);
    cudaFuncSetAttribute(edge_conv_kernel<64, false>,
                         cudaFuncAttributeMaxDynamicSharedMemorySize, smem64f);
    cudaFuncSetAttribute(knn_mma_kernel,
                         cudaFuncAttributeMaxDynamicSharedMemorySize, SM_KNN_TOTAL);

    build_x0_kernel<<<(BATCH * NPTS * 6 + 255) / 256, 256>>>(targets, x0);

    knn6_split_kernel<<<dim3(NPTS / 128, NSPLIT6, BATCH), 128>>>(x0, sd, si);
    knn_merge_kernel<<<(BATCH * NPTS + 255) / 256, 256>>>(sd, si, idx);
    edge_conv_kernel<6, true><<<BATCH * NPTS / 16, 512, smem6t>>>(x0, idx, w[0], w[1], pa, 0, 1, x1);

    cvt_norm_kernel<<<BATCH * NPTS * 32 / 256, 256>>>(x1, xhi, xlo, nrm);
    knn_mma_kernel<<<dim3(NPTS / 128, BATCH), 128, SM_KNN_TOTAL>>>(xhi, xlo, nrm, idx);
    edge_conv_kernel<64, true><<<BATCH * NPTS / 16, 512, smem64t>>>(x1, idx, w[2], w[3], pa, 2, 3, x2);

    cvt_norm_kernel<<<BATCH * NPTS * 32 / 256, 256>>>(x2, xhi, xlo, nrm);
    knn_mma_kernel<<<dim3(NPTS / 128, BATCH), 128, SM_KNN_TOTAL>>>(xhi, xlo, nrm, idx);
    edge_conv_kernel<64, false><<<BATCH * NPTS / 16, 512, smem64f>>>(x2, idx, w[4], nullptr, pa, 4, 4, x3);

    concat_x4_kernel<<<(BATCH * NPTS * 192 + 255) / 256, 256>>>(x1, x2, x3, x4);

    gemm_prelu_kernel<<<dim3(BATCH * NPTS / 64, 1024 / 64), 128>>>(x4, w[5], x5, nullptr, pa, 5, 192, 1024);
    max1_kernel<<<dim3(32, BATCH), 1024>>>(x5, pmax);
    max2_kernel<<<BATCH, 1024>>>(pmax, x5max);
    bias_kernel<<<BATCH, 256>>>(x5max, w[6], bias);

    gemm_prelu_kernel<<<dim3(BATCH * NPTS / 64, 256 / 64), 128>>>(x4, w[6], y1, bias, pa, 6, 192, 256);
    gemm_prelu_kernel<<<dim3(BATCH * NPTS / 64, 256 / 64), 128>>>(y1, w[7], y2, nullptr, pa, 7, 256, 256);
    gemm_prelu_kernel<<<dim3(BATCH * NPTS / 64, 128 / 64), 128>>>(y2, w[8], y3, nullptr, pa, 8, 256, 128);
    final_kernel<<<BATCH * NPTS / 4, 128>>>(y3, w[9], pa, out);

    (void)in_sizes; (void)n_in; (void)out_size;
}

// round 16
// speedup vs baseline: 1.6776x; 1.0570x over previous
#include <cuda_runtime.h>
#include <cuda_bf16.h>
#include <math_constants.h>
#include <cstdint>

#define NPTS 8192
#define BATCH 4
#define KNNK 10
#define NSPLIT6 4
#define SPLITLEN6 (NPTS / NSPLIT6)

// ---------------- scratch arena (no allocation allowed) ----------------
#define O_X0     0u
#define O_IDX    196608u
#define O_X1     524288u
#define O_X2     2621440u
#define O_X3     4718592u
#define O_X4     6815744u
#define O_X5     13107200u
#define O_PMAX   46661632u
#define O_X5MAX  46792704u
#define O_BIAS   46796800u
#define O_Y1     46797824u
#define O_Y2     55186432u
#define O_Y3     63575040u
#define O_XHI    67769344u   // 2,097,152 bf16 = 1,048,576 floats
#define O_XLO    68817920u
#define O_NORM   69866496u   // 32768 floats
#define O_SD     69899264u   // 4*8192*4*10 = 1,310,720 floats
#define O_SI     71209984u   // 1,310,720 ints
#define SCRATCH_FLOATS 72520704u

__device__ __align__(16) float g_scratch[SCRATCH_FLOATS];

// ---------------- f32x2 packed helpers (sm_103a) ----------------
__device__ __forceinline__ void unpack2(unsigned long long v, float& lo, float& hi) {
    asm("mov.b64 {%0, %1}, %2;" : "=f"(lo), "=f"(hi) : "l"(v));
}
__device__ __forceinline__ unsigned long long fma2(unsigned long long a,
                                                   unsigned long long b,
                                                   unsigned long long c) {
    unsigned long long d;
    asm("fma.rn.f32x2 %0, %1, %2, %3;" : "=l"(d) : "l"(a), "l"(b), "l"(c));
    return d;
}

// ---------------- warp-mma helpers (target-independent PTX) ----------------
__device__ __forceinline__ uint32_t smem_to_u32(const void* p) {
    uint32_t a;
    asm("{ .reg .u64 t; cvta.to.shared.u64 t, %1; cvt.u32.u64 %0, t; }" : "=r"(a) : "l"(p));
    return a;
}
#define SMEM_SWIZZLE_128B(o) ((o) ^ (((o) >> 3) & 0x70))

__device__ __forceinline__ void ldsm_x4(uint32_t a[4], uint32_t addr) {
    asm volatile("ldmatrix.sync.aligned.m8n8.x4.shared.b16 {%0,%1,%2,%3}, [%4];"
        : "=r"(a[0]), "=r"(a[1]), "=r"(a[2]), "=r"(a[3]) : "r"(addr));
}
__device__ __forceinline__ void ldsm_x2(uint32_t a[2], uint32_t addr) {
    asm volatile("ldmatrix.sync.aligned.m8n8.x2.shared.b16 {%0,%1}, [%2];"
        : "=r"(a[0]), "=r"(a[1]) : "r"(addr));
}
__device__ __forceinline__ void mma16816(float c[4], const uint32_t a[4], const uint32_t b[2]) {
    asm volatile("mma.sync.aligned.m16n8k16.row.col.f32.bf16.bf16.f32 "
        "{%0,%1,%2,%3}, {%4,%5,%6,%7}, {%8,%9}, {%0,%1,%2,%3};"
        : "+f"(c[0]), "+f"(c[1]), "+f"(c[2]), "+f"(c[3])
        : "r"(a[0]), "r"(a[1]), "r"(a[2]), "r"(a[3]), "r"(b[0]), "r"(b[1]));
}

// ---------------- build x0 = concat(targets, targets) ----------------
__global__ void build_x0_kernel(const float* __restrict__ t, float* __restrict__ x0) {
    int i = blockIdx.x * blockDim.x + threadIdx.x;
    if (i < BATCH * NPTS * 6) {
        int pt = i / 6, c = i % 6;
        x0[i] = t[pt * 3 + (c < 3 ? c : c - 3)];
    }
}

// ---------------- fused fp32 -> bf16 hi/lo split + squared norm (warp/point) ----------------
__global__ void cvt_norm_kernel(const float* __restrict__ x,
                                __nv_bfloat16* __restrict__ hi,
                                __nv_bfloat16* __restrict__ lo,
                                float* __restrict__ norms) {
    int gw = (blockIdx.x * 256 + threadIdx.x) >> 5;   // warp = point
    int lane = threadIdx.x & 31;
    if (gw >= BATCH * NPTS) return;
    float2 v = *(const float2*)(x + (size_t)gw * 64 + lane * 2);
    __nv_bfloat16 h0 = __float2bfloat16(v.x);
    __nv_bfloat16 h1 = __float2bfloat16(v.y);
    __nv_bfloat16 l0 = __float2bfloat16(v.x - __bfloat162float(h0));
    __nv_bfloat16 l1 = __float2bfloat16(v.y - __bfloat162float(h1));
    *(__nv_bfloat162*)(hi + (size_t)gw * 64 + lane * 2) = __nv_bfloat162(h0, h1);
    *(__nv_bfloat162*)(lo + (size_t)gw * 64 + lane * 2) = __nv_bfloat162(l0, l1);
    float s = fmaf(v.x, v.x, v.y * v.y);
    #pragma unroll
    for (int o = 16; o > 0; o >>= 1) s += __shfl_down_sync(0xffffffffu, s, o);
    if (lane == 0) norms[gw] = s;
}

// ---------------- KNN C=6: candidate-split (R13-proven) ----------------
__global__ void knn6_split_kernel(const float* __restrict__ x,
                                  float* __restrict__ sd, int* __restrict__ si) {
    __shared__ float tile[128 * 6];
    __shared__ float tnorm[128];
    const int b = blockIdx.z;
    const int sp = blockIdx.y;
    const int q = blockIdx.x * 128 + threadIdx.x;
    const float* xb = x + (size_t)b * NPTS * 6;
    const int cand0 = sp * SPLITLEN6;

    float qf[6];
    float qn = 0.f;
    #pragma unroll
    for (int c = 0; c < 6; c++) { qf[c] = xb[q * 6 + c]; qn = fmaf(qf[c], qf[c], qn); }

    float bd[KNNK]; int bi[KNNK];
    #pragma unroll
    for (int i = 0; i < KNNK; i++) { bd[i] = CUDART_INF_F; bi[i] = 0; }

    for (int t0 = cand0; t0 < cand0 + SPLITLEN6; t0 += 128) {
        __syncthreads();
        for (int i = threadIdx.x; i < 128 * 6; i += 128) tile[i] = xb[t0 * 6 + i];
        __syncthreads();
        {
            float s = 0.f;
            #pragma unroll
            for (int c = 0; c < 6; c++) {
                float v = tile[threadIdx.x * 6 + c];
                s = fmaf(v, v, s);
            }
            tnorm[threadIdx.x] = s;
        }
        __syncthreads();
        for (int j = 0; j < 128; j++) {
            float d0 = 0.f, d1 = 0.f;
            #pragma unroll
            for (int c = 0; c < 6; c += 2) {
                d0 = fmaf(qf[c + 0], tile[j * 6 + c + 0], d0);
                d1 = fmaf(qf[c + 1], tile[j * 6 + c + 1], d1);
            }
            float d = qn + tnorm[j] - 2.f * (d0 + d1);
            if (d < bd[KNNK - 1]) {
                bd[KNNK - 1] = d; bi[KNNK - 1] = t0 + j;
                #pragma unroll
                for (int s = KNNK - 1; s > 0; s--) {
                    if (bd[s] < bd[s - 1]) {
                        float td = bd[s]; bd[s] = bd[s - 1]; bd[s - 1] = td;
                        int   ti = bi[s]; bi[s] = bi[s - 1]; bi[s - 1] = ti;
                    }
                }
            }
        }
    }
    size_t o = (((size_t)b * NPTS + q) * NSPLIT6 + sp) * KNNK;
    #pragma unroll
    for (int i = 0; i < KNNK; i++) { sd[o + i] = bd[i]; si[o + i] = bi[i]; }
}

// merge NSPLIT6 partial top-10 lists into final indices (R13-proven)
__global__ void knn_merge_kernel(const float* __restrict__ sd, const int* __restrict__ si,
                                 int* __restrict__ idxout) {
    int p = blockIdx.x * 256 + threadIdx.x;
    if (p >= BATCH * NPTS) return;
    const float* d = sd + (size_t)p * NSPLIT6 * KNNK;
    const int* ix = si + (size_t)p * NSPLIT6 * KNNK;
    float bd[KNNK]; int bi[KNNK];
    #pragma unroll
    for (int i = 0; i < KNNK; i++) { bd[i] = CUDART_INF_F; bi[i] = 0; }
    #pragma unroll 4
    for (int s = 0; s < NSPLIT6 * KNNK; s++) {
        float dv = d[s];
        if (dv < bd[KNNK - 1]) {
            bd[KNNK - 1] = dv; bi[KNNK - 1] = ix[s];
            #pragma unroll
            for (int t = KNNK - 1; t > 0; t--) {
                if (bd[t] < bd[t - 1]) {
                    float td = bd[t]; bd[t] = bd[t - 1]; bd[t - 1] = td;
                    int   ti = bi[t]; bi[t] = bi[t - 1]; bi[t - 1] = ti;
                }
            }
        }
    }
    int* o = idxout + (size_t)p * KNNK;
    #pragma unroll
    for (int i = 0; i < KNNK; i++) o[i] = bi[i];
}

// ---------------- KNN C=64 on tensor cores (R8-proven, byte-identical) ----------------
#define SM_AHI   0
#define SM_ALO   16384
#define SM_BHI   32768
#define SM_BLO   40960
#define SM_TN    49152
#define SM_DIST  49408
#define SM_KNN_TOTAL 83200

__global__ __launch_bounds__(128)
void knn_mma_kernel(const __nv_bfloat16* __restrict__ xhi,
                    const __nv_bfloat16* __restrict__ xlo,
                    const float* __restrict__ norms,
                    int* __restrict__ idxout) {
    extern __shared__ char smem[];
    const uint32_t sb = smem_to_u32(smem);
    float* tnS  = (float*)(smem + SM_TN);
    float* dist = (float*)(smem + SM_DIST);
    const int tid = threadIdx.x, w = tid >> 5, l = tid & 31;
    const int b = blockIdx.y, q0 = blockIdx.x * 128;
    const __nv_bfloat16* xh = xhi + (size_t)b * NPTS * 64;
    const __nv_bfloat16* xl = xlo + (size_t)b * NPTS * 64;
    const float* nrm = norms + (size_t)b * NPTS;

    {
        const uint4* sH = (const uint4*)(xh + (size_t)(q0 + tid) * 64);
        const uint4* sL = (const uint4*)(xl + (size_t)(q0 + tid) * 64);
        #pragma unroll
        for (int k = 0; k < 8; k++) {
            uint32_t off = SMEM_SWIZZLE_128B((uint32_t)(tid * 128 + k * 16));
            *(uint4*)(smem + SM_AHI + off) = sH[k];
            *(uint4*)(smem + SM_ALO + off) = sL[k];
        }
    }

    float bd[KNNK]; int bi[KNNK];
    #pragma unroll
    for (int i = 0; i < KNNK; i++) { bd[i] = CUDART_INF_F; bi[i] = 0; }

    const int arow = (l & 15);
    const int akh  = (l >> 4);
    const int brow = (l & 7);
    const int bkh  = (l >> 3) & 1;

    for (int tile = 0; tile < NPTS / 64; tile++) {
        const int t0 = tile * 64;
        __syncthreads();
        {
            int r = tid & 63;
            const __nv_bfloat16* src = (tid < 64 ? xh : xl) + (size_t)(t0 + r) * 64;
            char* dstb = smem + (tid < 64 ? SM_BHI : SM_BLO);
            const uint4* s4 = (const uint4*)src;
            #pragma unroll
            for (int k = 0; k < 8; k++) {
                uint32_t off = SMEM_SWIZZLE_128B((uint32_t)(r * 128 + k * 16));
                *(uint4*)(dstb + off) = s4[k];
            }
            if (tid < 64) tnS[tid] = nrm[t0 + tid];
        }
        __syncthreads();

        float acc[2][8][4];
        #pragma unroll
        for (int mt = 0; mt < 2; mt++)
            #pragma unroll
            for (int nt = 0; nt < 8; nt++)
                #pragma unroll
                for (int c = 0; c < 4; c++) acc[mt][nt][c] = 0.f;

        #pragma unroll
        for (int ks = 0; ks < 4; ks++) {
            uint32_t aH[2][4], aL[2][4];
            #pragma unroll
            for (int mt = 0; mt < 2; mt++) {
                uint32_t ro = (uint32_t)((w * 32 + mt * 16 + arow) * 128 + ks * 32 + akh * 16);
                uint32_t so = SMEM_SWIZZLE_128B(ro);
                ldsm_x4(aH[mt], sb + SM_AHI + so);
                ldsm_x4(aL[mt], sb + SM_ALO + so);
            }
            #pragma unroll
            for (int nt = 0; nt < 8; nt++) {
                uint32_t ro = (uint32_t)((nt * 8 + brow) * 128 + ks * 32 + bkh * 16);
                uint32_t so = SMEM_SWIZZLE_128B(ro);
                uint32_t bH[2], bL[2];
                ldsm_x2(bH, sb + SM_BHI + so);
                ldsm_x2(bL, sb + SM_BLO + so);
                #pragma unroll
                for (int mt = 0; mt < 2; mt++) {
                    mma16816(acc[mt][nt], aH[mt], bH);
                    mma16816(acc[mt][nt], aH[mt], bL);
                    mma16816(acc[mt][nt], aL[mt], bH);
                }
            }
        }

        #pragma unroll
        for (int mt = 0; mt < 2; mt++) {
            int r0 = w * 32 + mt * 16 + (l >> 2);
            #pragma unroll
            for (int nt = 0; nt < 8; nt++) {
                int cn = nt * 8 + (l & 3) * 2;
                *(float2*)(dist + (size_t)r0 * 66 + cn) =
                    make_float2(acc[mt][nt][0], acc[mt][nt][1]);
                *(float2*)(dist + (size_t)(r0 + 8) * 66 + cn) =
                    make_float2(acc[mt][nt][2], acc[mt][nt][3]);
            }
        }
        __syncthreads();

        const float* drow = dist + (size_t)tid * 66;
        #pragma unroll 8
        for (int j = 0; j < 64; j++) {
            float d = fmaf(-2.f, drow[j], tnS[j]);
            if (d < bd[KNNK - 1]) {
                bd[KNNK - 1] = d; bi[KNNK - 1] = t0 + j;
                #pragma unroll
                for (int s = KNNK - 1; s > 0; s--) {
                    if (bd[s] < bd[s - 1]) {
                        float td = bd[s]; bd[s] = bd[s - 1]; bd[s - 1] = td;
                        int   ti = bi[s]; bi[s] = bi[s - 1]; bi[s - 1] = ti;
                    }
                }
            }
        }
    }

    int* o = idxout + ((size_t)b * NPTS + q0 + tid) * KNNK;
    #pragma unroll
    for (int i = 0; i < KNNK; i++) o[i] = bi[i];
}

// ---------------- edge conv: neighbor-paired, center-hoisted, dup-packed f32x2 ----------------
// Processes neighbors in pairs so each weight LDS.64 feeds two FMA2s.
// Per-neighbor accumulation chains identical to the unpaired version.
template<int C, bool TWO>
__global__ void edge_conv_kernel(const float* __restrict__ x, const int* __restrict__ knn,
                                 const float* __restrict__ w1, const float* __restrict__ w2,
                                 const float* __restrict__ pa, int ai1, int ai2,
                                 float* __restrict__ out) {
    constexpr int F = 2 * C;
    constexpr int PPB = 16;
    constexpr int WSLOT = 6 * C + (TWO ? 256 : 0);   // cdup + ddupA + ddupB (+ hdupA + hdupB)
    extern __shared__ float smf[];
    float* ws1 = smf;
    float* ws2 = ws1 + F * 64;
    float* wsl = ws2 + (TWO ? 4096 : 0);

    int tid = threadIdx.x;
    for (int i = tid; i < F * 64; i += 512) ws1[i] = w1[i];
    if (TWO) for (int i = tid; i < 4096; i += 512) ws2[i] = w2[i];
    float a1 = pa[ai1];
    float a2 = TWO ? pa[ai2] : 0.f;
    __syncthreads();

    int g = tid >> 5, lt = tid & 31;
    size_t pt = (size_t)blockIdx.x * PPB + g;
    int b = (int)(pt / NPTS);
    int n = (int)(pt % NPTS);
    const float* xb = x + (size_t)b * NPTS * C;
    const int* nbr = knn + pt * KNNK;
    float* cdup  = wsl + g * WSLOT;
    float* ddupA = cdup + 2 * C;
    float* ddupB = ddupA + 2 * C;
    float* hdupA = ddupB + 2 * C;
    float* hdupB = hdupA + 128;

    for (int c = lt; c < C; c += 32) {
        float v = xb[(size_t)n * C + c];
        *(float2*)(cdup + 2 * c) = make_float2(v, v);
    }
    __syncwarp();

    // neighbor-invariant contribution: xr @ w1[C:]
    unsigned long long cc = 0ull;
    #pragma unroll 8
    for (int c = 0; c < C; c++) {
        unsigned long long fd = *(const unsigned long long*)(cdup + 2 * c);
        unsigned long long wp = *(const unsigned long long*)(ws1 + (size_t)(C + c) * 64 + 2 * lt);
        cc = fma2(fd, wp, cc);
    }

    float mx0 = -CUDART_INF_F, mx1 = -CUDART_INF_F;
    #pragma unroll
    for (int jp = 0; jp < KNNK; jp += 2) {
        int nbA = nbr[jp], nbB = nbr[jp + 1];
        __syncwarp();
        for (int c = lt; c < C; c += 32) {
            float ctr = cdup[2 * c];
            float vA = xb[(size_t)nbA * C + c] - ctr;
            float vB = xb[(size_t)nbB * C + c] - ctr;
            *(float2*)(ddupA + 2 * c) = make_float2(vA, vA);
            *(float2*)(ddupB + 2 * c) = make_float2(vB, vB);
        }
        __syncwarp();
        unsigned long long accA = cc, accB = cc;
        #pragma unroll 8
        for (int c = 0; c < C; c++) {
            unsigned long long wp = *(const unsigned long long*)(ws1 + (size_t)c * 64 + 2 * lt);
            unsigned long long fA = *(const unsigned long long*)(ddupA + 2 * c);
            unsigned long long fB = *(const unsigned long long*)(ddupB + 2 * c);
            accA = fma2(fA, wp, accA);
            accB = fma2(fB, wp, accB);
        }
        float sA0, sA1, sB0, sB1;
        unpack2(accA, sA0, sA1);
        unpack2(accB, sB0, sB1);
        float hA0 = sA0 >= 0.f ? sA0 : a1 * sA0;
        float hA1 = sA1 >= 0.f ? sA1 : a1 * sA1;
        float hB0 = sB0 >= 0.f ? sB0 : a1 * sB0;
        float hB1 = sB1 >= 0.f ? sB1 : a1 * sB1;
        if (TWO) {
            *(float2*)(hdupA + 4 * lt)     = make_float2(hA0, hA0);
            *(float2*)(hdupA + 4 * lt + 2) = make_float2(hA1, hA1);
            *(float2*)(hdupB + 4 * lt)     = make_float2(hB0, hB0);
            *(float2*)(hdupB + 4 * lt + 2) = make_float2(hB1, hB1);
            __syncwarp();
            unsigned long long acc2A = 0ull, acc2B = 0ull;
            #pragma unroll 8
            for (int c = 0; c < 64; c++) {
                unsigned long long wp = *(const unsigned long long*)(ws2 + (size_t)c * 64 + 2 * lt);
                unsigned long long fA = *(const unsigned long long*)(hdupA + 2 * c);
                unsigned long long fB = *(const unsigned long long*)(hdupB + 2 * c);
                acc2A = fma2(fA, wp, acc2A);
                acc2B = fma2(fB, wp, acc2B);
            }
            float tA0, tA1, tB0, tB1;
            unpack2(acc2A, tA0, tA1);
            unpack2(acc2B, tB0, tB1);
            hA0 = tA0 >= 0.f ? tA0 : a2 * tA0;
            hA1 = tA1 >= 0.f ? tA1 : a2 * tA1;
            hB0 = tB0 >= 0.f ? tB0 : a2 * tB0;
            hB1 = tB1 >= 0.f ? tB1 : a2 * tB1;
        }
        mx0 = fmaxf(fmaxf(mx0, hA0), hB0);
        mx1 = fmaxf(fmaxf(mx1, hA1), hB1);
    }
    *(float2*)(out + pt * 64 + 2 * lt) = make_float2(mx0, mx1);
}

// ---------------- concat x4 = [x1|x2|x3] ----------------
__global__ void concat_x4_kernel(const float* __restrict__ x1, const float* __restrict__ x2,
                                 const float* __restrict__ x3, float* __restrict__ x4) {
    int i = blockIdx.x * 256 + threadIdx.x;
    if (i < BATCH * NPTS * 192) {
        int pt = i / 192, c = i % 192;
        float v = (c < 64) ? x1[pt * 64 + c]
                : (c < 128) ? x2[pt * 64 + c - 64]
                : x3[pt * 64 + c - 128];
        x4[i] = v;
    }
}

// ---------------- SGEMM + per-batch bias + PReLU epilogue (R2-proven) ----------------
__global__ void gemm_prelu_kernel(const float* __restrict__ A, const float* __restrict__ B,
                                  float* __restrict__ C, const float* __restrict__ bias,
                                  const float* __restrict__ pa, int aidx,
                                  int K, int Nc) {
    __shared__ float As[16][64];
    __shared__ float Bs[16][64];
    int tid = threadIdx.x;
    int tx = tid & 15, ty = tid >> 4;
    int m0 = blockIdx.x * 64, n0 = blockIdx.y * 64;

    float acc[8][4];
    #pragma unroll
    for (int r = 0; r < 8; r++)
        #pragma unroll
        for (int c = 0; c < 4; c++) acc[r][c] = 0.f;

    for (int k0 = 0; k0 < K; k0 += 16) {
        #pragma unroll
        for (int l = 0; l < 2; l++) {
            int i = tid * 2 + l;
            int m = i >> 2, kc = (i & 3) * 4;
            float4 v = *(const float4*)(A + (size_t)(m0 + m) * K + k0 + kc);
            As[kc + 0][m] = v.x; As[kc + 1][m] = v.y;
            As[kc + 2][m] = v.z; As[kc + 3][m] = v.w;
            int kb = i >> 4, nb = (i & 15) * 4;
            float4 w = *(const float4*)(B + (size_t)(k0 + kb) * Nc + n0 + nb);
            *(float4*)(&Bs[kb][nb]) = w;
        }
        __syncthreads();
        #pragma unroll
        for (int kk = 0; kk < 16; kk++) {
            float a[8], bb[4];
            #pragma unroll
            for (int r = 0; r < 8; r++) a[r] = As[kk][ty * 8 + r];
            #pragma unroll
            for (int c = 0; c < 4; c++) bb[c] = Bs[kk][tx * 4 + c];
            #pragma unroll
            for (int r = 0; r < 8; r++)
                #pragma unroll
                for (int c = 0; c < 4; c++)
                    acc[r][c] = fmaf(a[r], bb[c], acc[r][c]);
        }
        __syncthreads();
    }

    float al = pa[aidx];
    #pragma unroll
    for (int r = 0; r < 8; r++) {
        size_t m = (size_t)m0 + ty * 8 + r;
        int n = n0 + tx * 4;
        float4 v;
        float bv0 = 0.f, bv1 = 0.f, bv2 = 0.f, bv3 = 0.f;
        if (bias) {
            const float* brow = bias + (m >> 13) * Nc;
            bv0 = brow[n]; bv1 = brow[n + 1]; bv2 = brow[n + 2]; bv3 = brow[n + 3];
        }
        float e0 = acc[r][0] + bv0, e1 = acc[r][1] + bv1;
        float e2 = acc[r][2] + bv2, e3 = acc[r][3] + bv3;
        v.x = e0 >= 0.f ? e0 : al * e0;
        v.y = e1 >= 0.f ? e1 : al * e1;
        v.z = e2 >= 0.f ? e2 : al * e2;
        v.w = e3 >= 0.f ? e3 : al * e3;
        *(float4*)(C + m * Nc + n) = v;
    }
}

// ---------------- global max over N + bias from w7 tail ----------------
__global__ void max1_kernel(const float* __restrict__ x5, float* __restrict__ pmax) {
    int b = blockIdx.y, chunk = blockIdx.x, c = threadIdx.x;
    const float* p = x5 + ((size_t)b * NPTS + (size_t)chunk * 256) * 1024 + c;
    float m = -CUDART_INF_F;
    for (int n = 0; n < 256; n++) m = fmaxf(m, p[(size_t)n * 1024]);
    pmax[((size_t)b * 32 + chunk) * 1024 + c] = m;
}
__global__ void max2_kernel(const float* __restrict__ pmax, float* __restrict__ x5max) {
    int b = blockIdx.x, c = threadIdx.x;
    float m = -CUDART_INF_F;
    for (int k = 0; k < 32; k++) m = fmaxf(m, pmax[((size_t)b * 32 + k) * 1024 + c]);
    x5max[b * 1024 + c] = m;
}
__global__ void bias_kernel(const float* __restrict__ x5max, const float* __restrict__ w7,
                            float* __restrict__ bias) {
    int b = blockIdx.x, j = threadIdx.x;
    float s = 0.f;
    for (int c = 0; c < 1024; c++)
        s = fmaf(x5max[b * 1024 + c], w7[(size_t)(192 + c) * 256 + j], s);
    bias[b * 256 + j] = s;
}

// ---------------- final 128->2 layer ----------------
__global__ void final_kernel(const float* __restrict__ y3, const float* __restrict__ w10,
                             const float* __restrict__ pa, float* __restrict__ out) {
    __shared__ float ws[256];
    int tid = threadIdx.x;
    ws[tid * 2] = w10[tid * 2];
    ws[tid * 2 + 1] = w10[tid * 2 + 1];
    __syncthreads();
    int warp = tid >> 5, lane = tid & 31;
    size_t pt = (size_t)blockIdx.x * 4 + warp;
    const float* row = y3 + pt * 128;
    float s0 = 0.f, s1 = 0.f;
    for (int c = lane; c < 128; c += 32) {
        float v = row[c];
        s0 = fmaf(v, ws[c * 2], s0);
        s1 = fmaf(v, ws[c * 2 + 1], s1);
    }
    #pragma unroll
    for (int o = 16; o > 0; o >>= 1) {
        s0 += __shfl_down_sync(0xffffffffu, s0, o);
        s1 += __shfl_down_sync(0xffffffffu, s1, o);
    }
    if (lane == 0) {
        float a = pa[9];
        out[pt * 2]     = s0 >= 0.f ? s0 : a * s0;
        out[pt * 2 + 1] = s1 >= 0.f ? s1 : a * s1;
    }
}

// ---------------- host orchestration ----------------
extern "C" void kernel_launch(void* const* d_in, const int* in_sizes, int n_in,
                              void* d_out, int out_size) {
    const float* targets = (const float*)d_in[0];
    const float* w[10];
    for (int i = 0; i < 10; i++) w[i] = (const float*)d_in[1 + i];
    const float* pa = (const float*)d_in[11];
    float* out = (float*)d_out;

    float* base = nullptr;
    cudaGetSymbolAddress((void**)&base, g_scratch);
    float* x0    = base + O_X0;
    int*   idx   = (int*)(base + O_IDX);
    float* x1    = base + O_X1;
    float* x2    = base + O_X2;
    float* x3    = base + O_X3;
    float* x4    = base + O_X4;
    float* x5    = base + O_X5;
    float* pmax  = base + O_PMAX;
    float* x5max = base + O_X5MAX;
    float* bias  = base + O_BIAS;
    float* y1    = base + O_Y1;
    float* y2    = base + O_Y2;
    float* y3    = base + O_Y3;
    __nv_bfloat16* xhi = (__nv_bfloat16*)(base + O_XHI);
    __nv_bfloat16* xlo = (__nv_bfloat16*)(base + O_XLO);
    float* nrm   = base + O_NORM;
    float* sd    = base + O_SD;
    int*   si    = (int*)(base + O_SI);

    // edge conv smem: ws1(F*64) [+ ws2 4096] + 16*WSLOT
    const int smem6t  = (12 * 64 + 4096 + 16 * (6 * 6 + 256)) * 4;     // 38144
    const int smem64t = (128 * 64 + 4096 + 16 * (6 * 64 + 256)) * 4;   // 90112
    const int smem64f = (128 * 64 + 16 * (6 * 64)) * 4;                // 57344

    cudaFuncSetAttribute(edge_conv_kernel<64, true>,
                         cudaFuncAttributeMaxDynamicSharedMemorySize, smem64t);
    cudaFuncSetAttribute(edge_conv_kernel<64, false>,
                         cudaFuncAttributeMaxDynamicSharedMemorySize, smem64f);
    cudaFuncSetAttribute(knn_mma_kernel,
                         cudaFuncAttributeMaxDynamicSharedMemorySize, SM_KNN_TOTAL);

    build_x0_kernel<<<(BATCH * NPTS * 6 + 255) / 256, 256>>>(targets, x0);

    knn6_split_kernel<<<dim3(NPTS / 128, NSPLIT6, BATCH), 128>>>(x0, sd, si);
    knn_merge_kernel<<<(BATCH * NPTS + 255) / 256, 256>>>(sd, si, idx);
    edge_conv_kernel<6, true><<<BATCH * NPTS / 16, 512, smem6t>>>(x0, idx, w[0], w[1], pa, 0, 1, x1);

    cvt_norm_kernel<<<BATCH * NPTS * 32 / 256, 256>>>(x1, xhi, xlo, nrm);
    knn_mma_kernel<<<dim3(NPTS / 128, BATCH), 128, SM_KNN_TOTAL>>>(xhi, xlo, nrm, idx);
    edge_conv_kernel<64, true><<<BATCH * NPTS / 16, 512, smem64t>>>(x1, idx, w[2], w[3], pa, 2, 3, x2);

    cvt_norm_kernel<<<BATCH * NPTS * 32 / 256, 256>>>(x2, xhi, xlo, nrm);
    knn_mma_kernel<<<dim3(NPTS / 128, BATCH), 128, SM_KNN_TOTAL>>>(xhi, xlo, nrm, idx);
    edge_conv_kernel<64, false><<<BATCH * NPTS / 16, 512, smem64f>>>(x2, idx, w[4], nullptr, pa, 4, 4, x3);

    concat_x4_kernel<<<(BATCH * NPTS * 192 + 255) / 256, 256>>>(x1, x2, x3, x4);

    gemm_prelu_kernel<<<dim3(BATCH * NPTS / 64, 1024 / 64), 128>>>(x4, w[5], x5, nullptr, pa, 5, 192, 1024);
    max1_kernel<<<dim3(32, BATCH), 1024>>>(x5, pmax);
    max2_kernel<<<BATCH, 1024>>>(pmax, x5max);
    bias_kernel<<<BATCH, 256>>>(x5max, w[6], bias);

    gemm_prelu_kernel<<<dim3(BATCH * NPTS / 64, 256 / 64), 128>>>(x4, w[6], y1, bias, pa, 6, 192, 256);
    gemm_prelu_kernel<<<dim3(BATCH * NPTS / 64, 256 / 64), 128>>>(y1, w[7], y2, nullptr, pa, 7, 256, 256);
    gemm_prelu_kernel<<<dim3(BATCH * NPTS / 64, 128 / 64), 128>>>(y2, w[8], y3, nullptr, pa, 8, 256, 128);
    final_kernel<<<BATCH * NPTS / 4, 128>>>(y3, w[9], pa, out);

    (void)in_sizes; (void)n_in; (void)out_size;
}